// round 9
// baseline (speedup 1.0000x reference)
#include <cuda_runtime.h>

typedef unsigned long long u64;

#define LAT    16
#define HID    50
#define HIDP   52          // hidden padded to multiple of 4
#define NQ     (HIDP/4)    // 13
#define TSMAX  132
#define BS     32          // threads per CTA (1 warp)
#define TANH_C 2.88539008177792681472f   // 2*log2(e)

// ---- packed f32x2 helpers (sm_100+; PTX-only) ----
static __device__ __forceinline__ u64 pk(float lo, float hi){
    u64 r; asm("mov.b64 %0, {%1,%2};" : "=l"(r) : "f"(lo), "f"(hi)); return r;
}
static __device__ __forceinline__ void upk(u64 v, float& lo, float& hi){
    asm("mov.b64 {%0,%1}, %2;" : "=f"(lo), "=f"(hi) : "l"(v));
}
static __device__ __forceinline__ u64 dup2(float x){ return pk(x, x); }
static __device__ __forceinline__ u64 fma2(u64 a, u64 b, u64 c){
    u64 d; asm("fma.rn.f32x2 %0, %1, %2, %3;" : "=l"(d) : "l"(a), "l"(b), "l"(c)); return d;
}
static __device__ __forceinline__ u64 add2(u64 a, u64 b){
    u64 d; asm("add.rn.f32x2 %0, %1, %2;" : "=l"(d) : "l"(a), "l"(b)); return d;
}
static __device__ __forceinline__ float hsum(u64 v){
    float lo, hi; upk(v, lo, hi); return lo + hi;
}

// tanh from PRE-SCALED argument a = 2*log2(e)*x : tanh(x) = 1 - 2/(2^a + 1)
static __device__ __forceinline__ float tanh_pre(float a){
    float e, r;
    asm("ex2.approx.f32 %0, %1;" : "=f"(e) : "f"(a));
    const float d = e + 1.0f;
    asm("rcp.approx.f32 %0, %1;" : "=f"(r) : "f"(d));
    return fmaf(-2.0f, r, 1.0f);
}

// ---- pipelined eval building blocks (all #pragma unroll'd, straight-line) ----

// W1 partials for 4 hidden units (offset l), both elements. pa seeded with
// packed (b*C, 0) bias; pb seeded 0 (bias added at activation time).
static __device__ __forceinline__ void w1_quad(
    const u64* __restrict__ za, const u64* __restrict__ zb,
    const float* __restrict__ sW1t, const u64* __restrict__ sb1p, int l,
    u64* __restrict__ pa, u64* __restrict__ pb)
{
    const ulonglong2 bp01 = *(const ulonglong2*)(sb1p + l);
    const ulonglong2 bp23 = *(const ulonglong2*)(sb1p + l + 2);
    pa[0] = bp01.x; pa[1] = bp01.y; pa[2] = bp23.x; pa[3] = bp23.y;
    pb[0] = 0; pb[1] = 0; pb[2] = 0; pb[3] = 0;
    const float* r = sW1t + l*LAT;
    #pragma unroll
    for (int q = 0; q < 4; ++q){
        #pragma unroll
        for (int row = 0; row < 4; ++row){
            const ulonglong2 w = *(const ulonglong2*)(r + row*LAT + 4*q);
            pa[row] = fma2(za[2*q], w.x, pa[row]);
            pa[row] = fma2(za[2*q+1], w.y, pa[row]);
            pb[row] = fma2(zb[2*q], w.x, pb[row]);
            pb[row] = fma2(zb[2*q+1], w.y, pb[row]);
        }
    }
}

// partials -> dup'd tanh activations (b-side gets its bias here, from sb1f)
static __device__ __forceinline__ void act_quad(
    const u64* __restrict__ pa, const u64* __restrict__ pb,
    const float* __restrict__ sb1f, int l,
    u64* __restrict__ hda, u64* __restrict__ hdb)
{
    const float4 bf = *(const float4*)(sb1f + l);
    hda[0] = dup2(tanh_pre(hsum(pa[0])));
    hdb[0] = dup2(tanh_pre(hsum(pb[0]) + bf.x));
    hda[1] = dup2(tanh_pre(hsum(pa[1])));
    hdb[1] = dup2(tanh_pre(hsum(pb[1]) + bf.y));
    hda[2] = dup2(tanh_pre(hsum(pa[2])));
    hdb[2] = dup2(tanh_pre(hsum(pb[2]) + bf.z));
    hda[3] = dup2(tanh_pre(hsum(pa[3])));
    hdb[3] = dup2(tanh_pre(hsum(pb[3]) + bf.w));
}

// W2 accumulation for 4 hidden units (offset l), both elements
static __device__ __forceinline__ void w2_quad(
    const u64* __restrict__ hda, const u64* __restrict__ hdb,
    const float* __restrict__ sW2, int l,
    u64* __restrict__ oa, u64* __restrict__ ob)
{
    #pragma unroll
    for (int r4 = 0; r4 < 4; ++r4){
        const float* wr = sW2 + (l + r4)*LAT;
        #pragma unroll
        for (int q = 0; q < 4; ++q){
            const ulonglong2 w = *(const ulonglong2*)(wr + 4*q);
            oa[2*q]     = fma2(hda[r4], w.x, oa[2*q]);
            oa[2*q + 1] = fma2(hda[r4], w.y, oa[2*q + 1]);
            ob[2*q]     = fma2(hdb[r4], w.x, ob[2*q]);
            ob[2*q + 1] = fma2(hdb[r4], w.y, ob[2*q + 1]);
        }
    }
}

// Dual-element ODE func, software-pipelined one quad deep:
// iteration lq overlaps [W1 loads+partials of lq] with [W2 FMAs of lq-1];
// tanh(lq) drains behind iteration lq+1's W1 block.
static __device__ __forceinline__ void ode_f2(
    const u64* __restrict__ za, const u64* __restrict__ zb,
    u64* __restrict__ oa, u64* __restrict__ ob,
    const float* __restrict__ sW1t,   // [HIDP][LAT] transposed, *TANH_C
    const u64*  __restrict__ sb1p,    // [HIDP] packed (b*C, 0)
    const float* __restrict__ sb1f,   // [HIDP] plain b*C
    const float* __restrict__ sW2,    // [HIDP][LAT]
    const float* __restrict__ sb2)    // [LAT]
{
    #pragma unroll
    for (int p = 0; p < 8; ++p){ oa[p] = *(const u64*)(sb2 + 2*p); ob[p] = oa[p]; }

    u64 pa[4], pb[4], hda[4], hdb[4];
    w1_quad(za, zb, sW1t, sb1p, 0, pa, pb);
    act_quad(pa, pb, sb1f, 0, hda, hdb);

    #pragma unroll 1
    for (int lq = 1; lq < NQ; ++lq){
        const int l = lq * 4;
        w1_quad(za, zb, sW1t, sb1p, l, pa, pb);   // current quad partials
        w2_quad(hda, hdb, sW2, l - 4, oa, ob);    // previous quad epilogue
        act_quad(pa, pb, sb1f, l, hda, hdb);      // current quad activations
    }
    w2_quad(hda, hdb, sW2, (NQ - 1) * 4, oa, ob); // drain
}

// Dual-element decoder: y = relu(z @ Wd1 + bd1) @ Wd2 + bd2 (short chains; unpipelined)
static __device__ __forceinline__ void dec_f2(
    const u64* __restrict__ za, const u64* __restrict__ zb,
    float& ya, float& yb,
    const float* __restrict__ sW1t, const u64* __restrict__ sb1p,
    const float* __restrict__ sb1f,
    const float* __restrict__ sw2, float b2)
{
    ya = b2; yb = b2;
    #pragma unroll 1
    for (int lq = 0; lq < NQ; ++lq){
        const int l = lq * 4;
        u64 pa[4], pb[4];
        w1_quad(za, zb, sW1t, sb1p, l, pa, pb);
        const float4 bf = *(const float4*)(sb1f + l);
        const float4 w2 = *(const float4*)(sw2 + l);
        ya = fmaf(fmaxf(hsum(pa[0]), 0.f), w2.x, ya);
        yb = fmaf(fmaxf(hsum(pb[0]) + bf.x, 0.f), w2.x, yb);
        ya = fmaf(fmaxf(hsum(pa[1]), 0.f), w2.y, ya);
        yb = fmaf(fmaxf(hsum(pb[1]) + bf.y, 0.f), w2.y, yb);
        ya = fmaf(fmaxf(hsum(pa[2]), 0.f), w2.z, ya);
        yb = fmaf(fmaxf(hsum(pb[2]) + bf.z, 0.f), w2.z, yb);
        ya = fmaf(fmaxf(hsum(pa[3]), 0.f), w2.w, ya);
        yb = fmaf(fmaxf(hsum(pb[3]) + bf.w, 0.f), w2.w, yb);
    }
}

__global__ void __launch_bounds__(BS) node_kernel(
    const float* __restrict__ x0,  const float* __restrict__ ts,
    const float* __restrict__ We1, const float* __restrict__ be1,
    const float* __restrict__ We2, const float* __restrict__ be2,
    const float* __restrict__ Wo1, const float* __restrict__ bo1,
    const float* __restrict__ Wo2, const float* __restrict__ bo2,
    const float* __restrict__ Wd1, const float* __restrict__ bd1,
    const float* __restrict__ Wd2, const float* __restrict__ bd2,
    float* __restrict__ out, int B, int T)
{
    __shared__ __align__(16) float sWo1t[HIDP*LAT];  // [l][i] transposed, *TANH_C
    __shared__ __align__(16) float sWo2 [HIDP*LAT];  // [l][j]
    __shared__ __align__(16) float sWd1t[HIDP*LAT];  // [l][i] transposed
    __shared__ __align__(16) float sWe2 [HIDP*LAT];  // [l][j]
    __shared__ __align__(16) float sWe1 [2*HIDP];
    __shared__ __align__(16) u64   sbo1p[HIDP];      // (bo1*C, 0) pairs
    __shared__ __align__(16) u64   sbd1p[HIDP];      // (bd1, 0) pairs
    __shared__ __align__(16) float sbo1f[HIDP];      // bo1*C plain
    __shared__ __align__(16) float sbd1f[HIDP];      // bd1 plain
    __shared__ __align__(16) float sbe1 [HIDP];
    __shared__ __align__(16) float sWd2 [HIDP];
    __shared__ __align__(16) float sbo2 [LAT];
    __shared__ __align__(16) float sbe2 [LAT];
    __shared__ __align__(16) u64   sZ [16*BS];       // per-thread z state (2 elems)
    __shared__ __align__(16) u64   sKs[16*BS];       // per-thread RK accumulator
    __shared__ float sT[TSMAX];

    const int tid = threadIdx.x;

    for (int idx = tid; idx < HIDP*LAT; idx += BS){
        const int l = idx / LAT, i = idx - l*LAT;
        const bool v = (l < HID);
        sWo1t[idx] = v ? Wo1[i*HID + l] * TANH_C : 0.f;   // transpose + prescale
        sWd1t[idx] = v ? Wd1[i*HID + l] : 0.f;            // transpose
        sWo2 [idx] = v ? Wo2[l*LAT + i] : 0.f;
        sWe2 [idx] = v ? We2[l*LAT + i] : 0.f;
    }
    for (int idx = tid; idx < HIDP; idx += BS){
        const bool v = (idx < HID);
        const float bo = v ? bo1[idx] * TANH_C : 0.f;
        const float bd = v ? bd1[idx] : 0.f;
        sbo1p[idx] = pk(bo, 0.f);
        sbd1p[idx] = pk(bd, 0.f);
        sbo1f[idx] = bo;
        sbd1f[idx] = bd;
        sbe1[idx] = v ? be1[idx] : 0.f;
        sWd2[idx] = v ? Wd2[idx] : 0.f;
        sWe1[idx]        = v ? We1[idx]       : 0.f;  // row 0 of (2,HID)
        sWe1[HIDP + idx] = v ? We1[HID + idx] : 0.f;  // row 1
    }
    if (tid < LAT){ sbo2[tid] = bo2[tid]; sbe2[tid] = be2[tid]; }
    const int tcap = (T < TSMAX) ? T : TSMAX;
    for (int idx = tid; idx < tcap; idx += BS) sT[idx] = ts[idx];
    __syncthreads();

    const int half = B >> 1;
    const int b0 = blockIdx.x * BS + tid;
    if (b0 >= half) return;
    const int b1 = b0 + half;

    u64* zA = &sZ[tid];             // elem-a state p at zA[p*BS]
    u64* zB = &sZ[8*BS + tid];
    u64* kA = &sKs[tid];
    u64* kB = &sKs[8*BS + tid];

    // ---- encoder for both elements (shared weight loads) ----
    {
        const float2 xa = *(const float2*)(x0 + 2*b0);
        const float2 xb = *(const float2*)(x0 + 2*b1);
        u64 ea[8], eb[8];
        #pragma unroll
        for (int p = 0; p < 8; ++p){ ea[p] = *(const u64*)(sbe2 + 2*p); eb[p] = ea[p]; }
        #pragma unroll 1
        for (int l = 0; l < HID; ++l){
            const float w0 = sWe1[l], w1 = sWe1[HIDP + l], bb = sbe1[l];
            const float hA = fmaxf(fmaf(xa.x, w0, fmaf(xa.y, w1, bb)), 0.f);
            const float hB = fmaxf(fmaf(xb.x, w0, fmaf(xb.y, w1, bb)), 0.f);
            const u64 hda = dup2(hA), hdb = dup2(hB);
            const float* wr = sWe2 + l*LAT;
            #pragma unroll
            for (int q = 0; q < 4; ++q){
                const ulonglong2 w2 = *(const ulonglong2*)(wr + 4*q);
                ea[2*q]     = fma2(hda, w2.x, ea[2*q]);
                ea[2*q + 1] = fma2(hda, w2.y, ea[2*q + 1]);
                eb[2*q]     = fma2(hdb, w2.x, eb[2*q]);
                eb[2*q + 1] = fma2(hdb, w2.y, eb[2*q + 1]);
            }
        }
        #pragma unroll
        for (int p = 0; p < 8; ++p){ zA[p*BS] = ea[p]; zB[p*BS] = eb[p]; }
    }

    u64 za[8], zb[8], ka[8], kb[8];
    const float bd2v = bd2[0];
    const u64 two = dup2(2.0f);

    #pragma unroll 1
    for (int t = 0; t < T; ++t){
        #pragma unroll
        for (int p = 0; p < 8; ++p){ za[p] = zA[p*BS]; zb[p] = zB[p*BS]; }

        float ya, yb;
        dec_f2(za, zb, ya, yb, sWd1t, sbd1p, sbd1f, sWd2, bd2v);
        out[(size_t)t * B + b0] = ya;
        out[(size_t)t * B + b1] = yb;
        if (t == T - 1) break;

        const float dt = (t + 1 < tcap) ? (sT[t+1] - sT[t]) : (ts[t+1] - ts[t]);
        const u64 hdt = dup2(0.5f * dt);
        const u64 fdt = dup2(dt);
        const u64 sdt = dup2(dt * (1.0f/6.0f));

        ode_f2(za, zb, ka, kb, sWo1t, sbo1p, sbo1f, sWo2, sbo2);   // k1
        #pragma unroll
        for (int p = 0; p < 8; ++p){
            kA[p*BS] = ka[p];                      kB[p*BS] = kb[p];
            za[p] = fma2(hdt, ka[p], zA[p*BS]);    zb[p] = fma2(hdt, kb[p], zB[p*BS]);
        }
        ode_f2(za, zb, ka, kb, sWo1t, sbo1p, sbo1f, sWo2, sbo2);   // k2
        #pragma unroll
        for (int p = 0; p < 8; ++p){
            kA[p*BS] = fma2(two, ka[p], kA[p*BS]); kB[p*BS] = fma2(two, kb[p], kB[p*BS]);
            za[p] = fma2(hdt, ka[p], zA[p*BS]);    zb[p] = fma2(hdt, kb[p], zB[p*BS]);
        }
        ode_f2(za, zb, ka, kb, sWo1t, sbo1p, sbo1f, sWo2, sbo2);   // k3
        #pragma unroll
        for (int p = 0; p < 8; ++p){
            kA[p*BS] = fma2(two, ka[p], kA[p*BS]); kB[p*BS] = fma2(two, kb[p], kB[p*BS]);
            za[p] = fma2(fdt, ka[p], zA[p*BS]);    zb[p] = fma2(fdt, kb[p], zB[p*BS]);
        }
        ode_f2(za, zb, ka, kb, sWo1t, sbo1p, sbo1f, sWo2, sbo2);   // k4
        #pragma unroll
        for (int p = 0; p < 8; ++p){
            zA[p*BS] = fma2(sdt, add2(kA[p*BS], ka[p]), zA[p*BS]);
            zB[p*BS] = fma2(sdt, add2(kB[p*BS], kb[p]), zB[p*BS]);
        }
    }
}

extern "C" void kernel_launch(void* const* d_in, const int* in_sizes, int n_in,
                              void* d_out, int out_size)
{
    const float* x0  = (const float*)d_in[0];
    const float* ts  = (const float*)d_in[1];
    const float* We1 = (const float*)d_in[2];
    const float* be1 = (const float*)d_in[3];
    const float* We2 = (const float*)d_in[4];
    const float* be2 = (const float*)d_in[5];
    const float* Wo1 = (const float*)d_in[6];
    const float* bo1 = (const float*)d_in[7];
    const float* Wo2 = (const float*)d_in[8];
    const float* bo2 = (const float*)d_in[9];
    const float* Wd1 = (const float*)d_in[10];
    const float* bd1 = (const float*)d_in[11];
    const float* Wd2 = (const float*)d_in[12];
    const float* bd2 = (const float*)d_in[13];

    const int B = in_sizes[0] / 2;   // (B, 2)
    const int T = in_sizes[1];       // (T,)
    const int half = B / 2;          // 2 elements per thread
    const int grid = (half + BS - 1) / BS;

    node_kernel<<<grid, BS>>>(x0, ts, We1, be1, We2, be2, Wo1, bo1,
                              Wo2, bo2, Wd1, bd1, Wd2, bd2,
                              (float*)d_out, B, T);
}

// round 12
// speedup vs baseline: 1.0849x; 1.0849x over previous
#include <cuda_runtime.h>

typedef unsigned long long u64;

#define LAT    16
#define HID    50
#define HIDP   52          // hidden padded to multiple of 4
#define NQ     13
#define NSPL   6           // warp0: quads [0,6) (units 0..23); warp1: [6,13)
#define TSMAX  132
#define TANH_C 2.88539008177792681472f   // 2*log2(e)

// ---- packed f32x2 helpers (sm_100+; PTX-only) ----
static __device__ __forceinline__ u64 pk(float lo, float hi){
    u64 r; asm("mov.b64 %0, {%1,%2};" : "=l"(r) : "f"(lo), "f"(hi)); return r;
}
static __device__ __forceinline__ void upk(u64 v, float& lo, float& hi){
    asm("mov.b64 {%0,%1}, %2;" : "=f"(lo), "=f"(hi) : "l"(v));
}
static __device__ __forceinline__ u64 dup2(float x){ return pk(x, x); }
static __device__ __forceinline__ u64 fma2(u64 a, u64 b, u64 c){
    u64 d; asm("fma.rn.f32x2 %0, %1, %2, %3;" : "=l"(d) : "l"(a), "l"(b), "l"(c)); return d;
}
static __device__ __forceinline__ u64 add2(u64 a, u64 b){
    u64 d; asm("add.rn.f32x2 %0, %1, %2;" : "=l"(d) : "l"(a), "l"(b)); return d;
}
static __device__ __forceinline__ float hsum(u64 v){
    float lo, hi; upk(v, lo, hi); return lo + hi;
}

// tanh from PRE-SCALED argument a = 2*log2(e)*x : tanh(x) = 1 - 2/(2^a + 1)
static __device__ __forceinline__ float tanh_pre(float a){
    float e, r;
    asm("ex2.approx.f32 %0, %1;" : "=f"(e) : "f"(a));
    const float d = e + 1.0f;
    asm("rcp.approx.f32 %0, %1;" : "=f"(r) : "f"(d));
    return fmaf(-2.0f, r, 1.0f);
}

// Partial ODE func over quads [lqb,lqe): accumulates tanh(z@W1+b1)@W2 into
// pre-seeded oa/ob for two batch elements sharing all weight loads.
// (R8's proven unroll-1 quad body; runtime warp-uniform bounds.)
static __device__ __forceinline__ void ode_part(
    const u64* __restrict__ za, const u64* __restrict__ zb,
    u64* __restrict__ oa, u64* __restrict__ ob,
    const float* __restrict__ sW1t,   // [HIDP][LAT] transposed, *TANH_C
    const u64*  __restrict__ sb1p,    // [HIDP] packed (b*C, 0)
    const float* __restrict__ sW2,    // [HIDP][LAT]
    int lqb, int lqe)
{
    #pragma unroll 1
    for (int lq = lqb; lq < lqe; ++lq){
        const int l = lq * 4;
        const ulonglong2 bp01 = *(const ulonglong2*)(sb1p + l);
        const ulonglong2 bp23 = *(const ulonglong2*)(sb1p + l + 2);
        u64 pa[4] = {bp01.x, bp01.y, bp23.x, bp23.y};
        u64 pb[4] = {bp01.x, bp01.y, bp23.x, bp23.y};
        const float* r = sW1t + l*LAT;
        #pragma unroll
        for (int q = 0; q < 4; ++q){
            #pragma unroll
            for (int row = 0; row < 4; ++row){
                const ulonglong2 w = *(const ulonglong2*)(r + row*LAT + 4*q);
                pa[row] = fma2(za[2*q], w.x, pa[row]);
                pa[row] = fma2(za[2*q+1], w.y, pa[row]);
                pb[row] = fma2(zb[2*q], w.x, pb[row]);
                pb[row] = fma2(zb[2*q+1], w.y, pb[row]);
            }
        }
        u64 hda[4], hdb[4];
        #pragma unroll
        for (int row = 0; row < 4; ++row){
            hda[row] = dup2(tanh_pre(hsum(pa[row])));
            hdb[row] = dup2(tanh_pre(hsum(pb[row])));
        }
        #pragma unroll
        for (int r4 = 0; r4 < 4; ++r4){
            const float* wr = sW2 + (l + r4)*LAT;
            #pragma unroll
            for (int q = 0; q < 4; ++q){
                const ulonglong2 w = *(const ulonglong2*)(wr + 4*q);
                oa[2*q]     = fma2(hda[r4], w.x, oa[2*q]);
                oa[2*q + 1] = fma2(hda[r4], w.y, oa[2*q + 1]);
                ob[2*q]     = fma2(hdb[r4], w.x, ob[2*q]);
                ob[2*q + 1] = fma2(hdb[r4], w.y, ob[2*q + 1]);
            }
        }
    }
}

// Partial decoder over quads [lqb,lqe): adds relu(z@Wd1+bd1)@Wd2 into ya/yb.
static __device__ __forceinline__ void dec_part(
    const u64* __restrict__ za, const u64* __restrict__ zb,
    float& ya, float& yb,
    const float* __restrict__ sW1t, const u64* __restrict__ sb1p,
    const float* __restrict__ sw2, int lqb, int lqe)
{
    #pragma unroll 1
    for (int lq = lqb; lq < lqe; ++lq){
        const int l = lq * 4;
        const ulonglong2 bp01 = *(const ulonglong2*)(sb1p + l);
        const ulonglong2 bp23 = *(const ulonglong2*)(sb1p + l + 2);
        u64 pa[4] = {bp01.x, bp01.y, bp23.x, bp23.y};
        u64 pb[4] = {bp01.x, bp01.y, bp23.x, bp23.y};
        const float* r = sW1t + l*LAT;
        #pragma unroll
        for (int q = 0; q < 4; ++q){
            #pragma unroll
            for (int row = 0; row < 4; ++row){
                const ulonglong2 w = *(const ulonglong2*)(r + row*LAT + 4*q);
                pa[row] = fma2(za[2*q], w.x, pa[row]);
                pa[row] = fma2(za[2*q+1], w.y, pa[row]);
                pb[row] = fma2(zb[2*q], w.x, pb[row]);
                pb[row] = fma2(zb[2*q+1], w.y, pb[row]);
            }
        }
        const float4 w2 = *(const float4*)(sw2 + l);
        ya = fmaf(fmaxf(hsum(pa[0]), 0.f), w2.x, ya);
        yb = fmaf(fmaxf(hsum(pb[0]), 0.f), w2.x, yb);
        ya = fmaf(fmaxf(hsum(pa[1]), 0.f), w2.y, ya);
        yb = fmaf(fmaxf(hsum(pb[1]), 0.f), w2.y, yb);
        ya = fmaf(fmaxf(hsum(pa[2]), 0.f), w2.z, ya);
        yb = fmaf(fmaxf(hsum(pb[2]), 0.f), w2.z, yb);
        ya = fmaf(fmaxf(hsum(pa[3]), 0.f), w2.w, ya);
        yb = fmaf(fmaxf(hsum(pb[3]), 0.f), w2.w, yb);
    }
}

__global__ void __launch_bounds__(64) node_kernel(
    const float* __restrict__ x0,  const float* __restrict__ ts,
    const float* __restrict__ We1, const float* __restrict__ be1,
    const float* __restrict__ We2, const float* __restrict__ be2,
    const float* __restrict__ Wo1, const float* __restrict__ bo1,
    const float* __restrict__ Wo2, const float* __restrict__ bo2,
    const float* __restrict__ Wd1, const float* __restrict__ bd1,
    const float* __restrict__ Wd2, const float* __restrict__ bd2,
    float* __restrict__ out, int B, int T)
{
    __shared__ __align__(16) float sWo1t[HIDP*LAT];  // [l][i] transposed, *TANH_C
    __shared__ __align__(16) float sWo2 [HIDP*LAT];  // [l][j]
    __shared__ __align__(16) float sWd1t[HIDP*LAT];  // [l][i] transposed
    __shared__ __align__(16) u64   sExch[16*32];     // warp1 partial o; We2 overlay (prologue)
    __shared__ __align__(16) u64   sZn  [16*32];     // next-z staging warp0 -> warp1
    __shared__ __align__(16) u64   sZb  [16*32];     // base z for step (warp0 private)
    __shared__ __align__(16) u64   sKs  [16*32];     // ksum (warp0 private)
    __shared__ __align__(16) float sWe1 [2*HIDP];
    __shared__ __align__(16) u64   sbo1p[HIDP];      // (bo1*C, 0) pairs
    __shared__ __align__(16) u64   sbd1p[HIDP];      // (bd1, 0) pairs
    __shared__ __align__(16) float sbe1 [HIDP];
    __shared__ __align__(16) float sWd2 [HIDP];
    __shared__ __align__(16) float sbo2 [LAT];
    __shared__ __align__(16) float sbe2 [LAT];
    __shared__ __align__(16) float sDecY[64];        // warp1 decoder partials
    __shared__ float sT[TSMAX];

    const int tid = threadIdx.x;
    float* sWe2 = (float*)sExch;                     // overlay: encoder-only

    for (int idx = tid; idx < HIDP*LAT; idx += 64){
        const int l = idx / LAT, i = idx - l*LAT;
        const bool v = (l < HID);
        sWo1t[idx] = v ? Wo1[i*HID + l] * TANH_C : 0.f;   // transpose + prescale
        sWd1t[idx] = v ? Wd1[i*HID + l] : 0.f;            // transpose
        sWo2 [idx] = v ? Wo2[l*LAT + i] : 0.f;
        sWe2 [idx] = v ? We2[l*LAT + i] : 0.f;
    }
    for (int idx = tid; idx < HIDP; idx += 64){
        const bool v = (idx < HID);
        sbo1p[idx] = pk(v ? bo1[idx] * TANH_C : 0.f, 0.f);
        sbd1p[idx] = pk(v ? bd1[idx] : 0.f, 0.f);
        sbe1[idx] = v ? be1[idx] : 0.f;
        sWd2[idx] = v ? Wd2[idx] : 0.f;
        sWe1[idx]        = v ? We1[idx]       : 0.f;  // row 0 of (2,HID)
        sWe1[HIDP + idx] = v ? We1[HID + idx] : 0.f;  // row 1
    }
    if (tid < LAT){ sbo2[tid] = bo2[tid]; sbe2[tid] = be2[tid]; }
    const int tcap = (T < TSMAX) ? T : TSMAX;
    for (int idx = tid; idx < tcap; idx += 64) sT[idx] = ts[idx];
    __syncthreads();

    const int lane = tid & 31, wid = tid >> 5;
    const int half = B >> 1;
    int b0 = blockIdx.x * 32 + lane;
    if (b0 >= half) b0 = half - 1;                   // clamp (keeps bars uniform)
    const int b1 = b0 + half;
    const int lqb = wid ? NSPL : 0;
    const int lqe = wid ? NQ   : NSPL;

    u64 za[8], zb[8];

    // ---- encoder: both warps compute z0 redundantly (shared weight loads) ----
    {
        const float2 xa = *(const float2*)(x0 + 2*b0);
        const float2 xb = *(const float2*)(x0 + 2*b1);
        #pragma unroll
        for (int p = 0; p < 8; ++p){ za[p] = *(const u64*)(sbe2 + 2*p); zb[p] = za[p]; }
        #pragma unroll 1
        for (int l = 0; l < HID; ++l){
            const float w0 = sWe1[l], w1 = sWe1[HIDP + l], bb = sbe1[l];
            const float hA = fmaxf(fmaf(xa.x, w0, fmaf(xa.y, w1, bb)), 0.f);
            const float hB = fmaxf(fmaf(xb.x, w0, fmaf(xb.y, w1, bb)), 0.f);
            const u64 hda = dup2(hA), hdb = dup2(hB);
            const float* wr = sWe2 + l*LAT;
            #pragma unroll
            for (int q = 0; q < 4; ++q){
                const ulonglong2 w2 = *(const ulonglong2*)(wr + 4*q);
                za[2*q]     = fma2(hda, w2.x, za[2*q]);
                za[2*q + 1] = fma2(hda, w2.y, za[2*q + 1]);
                zb[2*q]     = fma2(hdb, w2.x, zb[2*q]);
                zb[2*q + 1] = fma2(hdb, w2.y, zb[2*q + 1]);
            }
        }
        if (wid == 0){
            #pragma unroll
            for (int p = 0; p < 8; ++p){
                sZb[p*32 + lane] = za[p]; sZb[(p+8)*32 + lane] = zb[p];
            }
        }
    }
    __syncthreads();   // fences encoder's We2-overlay reads before exch reuse

    const float bd2v = bd2[0];
    const u64 two = dup2(2.0f);

    #pragma unroll 1
    for (int t = 0; t < T; ++t){
        // ---- decoder: split across warps, warp0 reduces + stores ----
        float ya = wid ? 0.f : bd2v;
        float yb = ya;
        dec_part(za, zb, ya, yb, sWd1t, sbd1p, sWd2, lqb, lqe);
        if (wid == 1){ sDecY[lane] = ya; sDecY[32 + lane] = yb; }
        __syncthreads();
        if (wid == 0){
            out[(size_t)t * B + b0] = ya + sDecY[lane];
            out[(size_t)t * B + b1] = yb + sDecY[32 + lane];
        }
        if (t == T - 1) break;

        const float dt = (t + 1 < tcap) ? (sT[t+1] - sT[t]) : (ts[t+1] - ts[t]);
        const u64 hdt = dup2(0.5f * dt);
        const u64 fdt = dup2(dt);
        const u64 sdt = dup2(dt * (1.0f/6.0f));

        u64 oa[8], ob[8], ka[8], kb[8];

        // ================= k1 =================
        #pragma unroll
        for (int p = 0; p < 8; ++p){
            oa[p] = wid ? 0ull : *(const u64*)(sbo2 + 2*p); ob[p] = oa[p];
        }
        ode_part(za, zb, oa, ob, sWo1t, sbo1p, sWo2, lqb, lqe);
        if (wid == 1){
            #pragma unroll
            for (int p = 0; p < 8; ++p){
                sExch[p*32 + lane] = oa[p]; sExch[(p+8)*32 + lane] = ob[p];
            }
        }
        __syncthreads();
        if (wid == 0){
            #pragma unroll
            for (int p = 0; p < 8; ++p){
                ka[p] = add2(oa[p], sExch[p*32 + lane]);
                kb[p] = add2(ob[p], sExch[(p+8)*32 + lane]);
            }
            #pragma unroll
            for (int p = 0; p < 8; ++p){
                sKs[p*32 + lane] = ka[p]; sKs[(p+8)*32 + lane] = kb[p];
                za[p] = fma2(hdt, ka[p], sZb[p*32 + lane]);
                zb[p] = fma2(hdt, kb[p], sZb[(p+8)*32 + lane]);
                sZn[p*32 + lane] = za[p]; sZn[(p+8)*32 + lane] = zb[p];
            }
        }
        __syncthreads();
        if (wid == 1){
            #pragma unroll
            for (int p = 0; p < 8; ++p){
                za[p] = sZn[p*32 + lane]; zb[p] = sZn[(p+8)*32 + lane];
            }
        }

        // ================= k2 =================
        #pragma unroll
        for (int p = 0; p < 8; ++p){
            oa[p] = wid ? 0ull : *(const u64*)(sbo2 + 2*p); ob[p] = oa[p];
        }
        ode_part(za, zb, oa, ob, sWo1t, sbo1p, sWo2, lqb, lqe);
        if (wid == 1){
            #pragma unroll
            for (int p = 0; p < 8; ++p){
                sExch[p*32 + lane] = oa[p]; sExch[(p+8)*32 + lane] = ob[p];
            }
        }
        __syncthreads();
        if (wid == 0){
            #pragma unroll
            for (int p = 0; p < 8; ++p){
                ka[p] = add2(oa[p], sExch[p*32 + lane]);
                kb[p] = add2(ob[p], sExch[(p+8)*32 + lane]);
            }
            #pragma unroll
            for (int p = 0; p < 8; ++p){
                sKs[p*32 + lane]     = fma2(two, ka[p], sKs[p*32 + lane]);
                sKs[(p+8)*32 + lane] = fma2(two, kb[p], sKs[(p+8)*32 + lane]);
                za[p] = fma2(hdt, ka[p], sZb[p*32 + lane]);
                zb[p] = fma2(hdt, kb[p], sZb[(p+8)*32 + lane]);
                sZn[p*32 + lane] = za[p]; sZn[(p+8)*32 + lane] = zb[p];
            }
        }
        __syncthreads();
        if (wid == 1){
            #pragma unroll
            for (int p = 0; p < 8; ++p){
                za[p] = sZn[p*32 + lane]; zb[p] = sZn[(p+8)*32 + lane];
            }
        }

        // ================= k3 =================
        #pragma unroll
        for (int p = 0; p < 8; ++p){
            oa[p] = wid ? 0ull : *(const u64*)(sbo2 + 2*p); ob[p] = oa[p];
        }
        ode_part(za, zb, oa, ob, sWo1t, sbo1p, sWo2, lqb, lqe);
        if (wid == 1){
            #pragma unroll
            for (int p = 0; p < 8; ++p){
                sExch[p*32 + lane] = oa[p]; sExch[(p+8)*32 + lane] = ob[p];
            }
        }
        __syncthreads();
        if (wid == 0){
            #pragma unroll
            for (int p = 0; p < 8; ++p){
                ka[p] = add2(oa[p], sExch[p*32 + lane]);
                kb[p] = add2(ob[p], sExch[(p+8)*32 + lane]);
            }
            #pragma unroll
            for (int p = 0; p < 8; ++p){
                sKs[p*32 + lane]     = fma2(two, ka[p], sKs[p*32 + lane]);
                sKs[(p+8)*32 + lane] = fma2(two, kb[p], sKs[(p+8)*32 + lane]);
                za[p] = fma2(fdt, ka[p], sZb[p*32 + lane]);
                zb[p] = fma2(fdt, kb[p], sZb[(p+8)*32 + lane]);
                sZn[p*32 + lane] = za[p]; sZn[(p+8)*32 + lane] = zb[p];
            }
        }
        __syncthreads();
        if (wid == 1){
            #pragma unroll
            for (int p = 0; p < 8; ++p){
                za[p] = sZn[p*32 + lane]; zb[p] = sZn[(p+8)*32 + lane];
            }
        }

        // ================= k4 + state update =================
        #pragma unroll
        for (int p = 0; p < 8; ++p){
            oa[p] = wid ? 0ull : *(const u64*)(sbo2 + 2*p); ob[p] = oa[p];
        }
        ode_part(za, zb, oa, ob, sWo1t, sbo1p, sWo2, lqb, lqe);
        if (wid == 1){
            #pragma unroll
            for (int p = 0; p < 8; ++p){
                sExch[p*32 + lane] = oa[p]; sExch[(p+8)*32 + lane] = ob[p];
            }
        }
        __syncthreads();
        if (wid == 0){
            #pragma unroll
            for (int p = 0; p < 8; ++p){
                ka[p] = add2(oa[p], sExch[p*32 + lane]);
                kb[p] = add2(ob[p], sExch[(p+8)*32 + lane]);
            }
            #pragma unroll
            for (int p = 0; p < 8; ++p){
                const u64 sa = add2(sKs[p*32 + lane], ka[p]);
                const u64 sb = add2(sKs[(p+8)*32 + lane], kb[p]);
                za[p] = fma2(sdt, sa, sZb[p*32 + lane]);
                zb[p] = fma2(sdt, sb, sZb[(p+8)*32 + lane]);
                sZb[p*32 + lane] = za[p]; sZb[(p+8)*32 + lane] = zb[p];
                sZn[p*32 + lane] = za[p]; sZn[(p+8)*32 + lane] = zb[p];
            }
        }
        __syncthreads();
        if (wid == 1){
            #pragma unroll
            for (int p = 0; p < 8; ++p){
                za[p] = sZn[p*32 + lane]; zb[p] = sZn[(p+8)*32 + lane];
            }
        }
    }
}

extern "C" void kernel_launch(void* const* d_in, const int* in_sizes, int n_in,
                              void* d_out, int out_size)
{
    const float* x0  = (const float*)d_in[0];
    const float* ts  = (const float*)d_in[1];
    const float* We1 = (const float*)d_in[2];
    const float* be1 = (const float*)d_in[3];
    const float* We2 = (const float*)d_in[4];
    const float* be2 = (const float*)d_in[5];
    const float* Wo1 = (const float*)d_in[6];
    const float* bo1 = (const float*)d_in[7];
    const float* Wo2 = (const float*)d_in[8];
    const float* bo2 = (const float*)d_in[9];
    const float* Wd1 = (const float*)d_in[10];
    const float* bd1 = (const float*)d_in[11];
    const float* Wd2 = (const float*)d_in[12];
    const float* bd2 = (const float*)d_in[13];

    const int B = in_sizes[0] / 2;   // (B, 2)
    const int T = in_sizes[1];       // (T,)
    const int half = B / 2;          // 2 elements per lane, 2 warps share them
    const int grid = (half + 31) / 32;

    node_kernel<<<grid, 64>>>(x0, ts, We1, be1, We2, be2, Wo1, bo1,
                              Wo2, bo2, Wd1, bd1, Wd2, bd2,
                              (float*)d_out, B, T);
}

// round 13
// speedup vs baseline: 1.4715x; 1.3563x over previous
#include <cuda_runtime.h>

typedef unsigned long long u64;

#define LAT    16
#define HID    50
#define HIDP   52          // hidden padded to multiple of 4
#define NQ     (HIDP/4)    // 13
#define TSMAX  132
#define BS     32          // threads per CTA (1 warp)

// ---- packed f32x2 helpers (sm_100+; PTX-only) ----
static __device__ __forceinline__ u64 pk(float lo, float hi){
    u64 r; asm("mov.b64 %0, {%1,%2};" : "=l"(r) : "f"(lo), "f"(hi)); return r;
}
static __device__ __forceinline__ void upk(u64 v, float& lo, float& hi){
    asm("mov.b64 {%0,%1}, %2;" : "=f"(lo), "=f"(hi) : "l"(v));
}
static __device__ __forceinline__ u64 dup2(float x){ return pk(x, x); }
static __device__ __forceinline__ u64 fma2(u64 a, u64 b, u64 c){
    u64 d; asm("fma.rn.f32x2 %0, %1, %2, %3;" : "=l"(d) : "l"(a), "l"(b), "l"(c)); return d;
}
static __device__ __forceinline__ u64 add2(u64 a, u64 b){
    u64 d; asm("add.rn.f32x2 %0, %1, %2;" : "=l"(d) : "l"(a), "l"(b)); return d;
}
static __device__ __forceinline__ float hsum(u64 v){
    float lo, hi; upk(v, lo, hi); return lo + hi;
}

// native single-MUFU tanh (sm_75+): 1 op instead of ex2+add+rcp+fma
static __device__ __forceinline__ float tanh_approx(float x){
    float y; asm("tanh.approx.f32 %0, %1;" : "=f"(y) : "f"(x)); return y;
}

// Dual-element ODE func: o = tanh(z @ W1 + b1) @ W2 + b2 for two states,
// sharing every weight load. b1 packed as (b, 0) pairs seeding both partials.
static __device__ __forceinline__ void ode_f2(
    const u64* __restrict__ za, const u64* __restrict__ zb,
    u64* __restrict__ oa, u64* __restrict__ ob,
    const float* __restrict__ sW1t,   // [HIDP][LAT] transposed
    const u64*  __restrict__ sb1p,    // [HIDP] packed (b, 0)
    const float* __restrict__ sW2,    // [HIDP][LAT]
    const float* __restrict__ sb2)    // [LAT]
{
    #pragma unroll
    for (int p = 0; p < 8; ++p){ oa[p] = *(const u64*)(sb2 + 2*p); ob[p] = oa[p]; }

    #pragma unroll 1
    for (int lq = 0; lq < NQ; ++lq){
        const int l = lq * 4;
        const ulonglong2 bp01 = *(const ulonglong2*)(sb1p + l);
        const ulonglong2 bp23 = *(const ulonglong2*)(sb1p + l + 2);
        u64 pa[4] = {bp01.x, bp01.y, bp23.x, bp23.y};
        u64 pb[4] = {bp01.x, bp01.y, bp23.x, bp23.y};
        const float* r = sW1t + l*LAT;
        #pragma unroll
        for (int q = 0; q < 4; ++q){
            #pragma unroll
            for (int row = 0; row < 4; ++row){
                const ulonglong2 w = *(const ulonglong2*)(r + row*LAT + 4*q);
                pa[row] = fma2(za[2*q], w.x, pa[row]);
                pa[row] = fma2(za[2*q+1], w.y, pa[row]);
                pb[row] = fma2(zb[2*q], w.x, pb[row]);
                pb[row] = fma2(zb[2*q+1], w.y, pb[row]);
            }
        }
        u64 hda[4], hdb[4];
        #pragma unroll
        for (int row = 0; row < 4; ++row){
            hda[row] = dup2(tanh_approx(hsum(pa[row])));
            hdb[row] = dup2(tanh_approx(hsum(pb[row])));
        }
        #pragma unroll
        for (int r4 = 0; r4 < 4; ++r4){
            const float* wr = sW2 + (l + r4)*LAT;
            #pragma unroll
            for (int q = 0; q < 4; ++q){
                const ulonglong2 w = *(const ulonglong2*)(wr + 4*q);
                oa[2*q]     = fma2(hda[r4], w.x, oa[2*q]);
                oa[2*q + 1] = fma2(hda[r4], w.y, oa[2*q + 1]);
                ob[2*q]     = fma2(hdb[r4], w.x, ob[2*q]);
                ob[2*q + 1] = fma2(hdb[r4], w.y, ob[2*q + 1]);
            }
        }
    }
}

// Dual-element decoder: y = relu(z @ Wd1 + bd1) @ Wd2 + bd2
static __device__ __forceinline__ void dec_f2(
    const u64* __restrict__ za, const u64* __restrict__ zb,
    float& ya, float& yb,
    const float* __restrict__ sW1t, const u64* __restrict__ sb1p,
    const float* __restrict__ sw2, float b2)
{
    ya = b2; yb = b2;
    #pragma unroll 1
    for (int lq = 0; lq < NQ; ++lq){
        const int l = lq * 4;
        const ulonglong2 bp01 = *(const ulonglong2*)(sb1p + l);
        const ulonglong2 bp23 = *(const ulonglong2*)(sb1p + l + 2);
        u64 pa[4] = {bp01.x, bp01.y, bp23.x, bp23.y};
        u64 pb[4] = {bp01.x, bp01.y, bp23.x, bp23.y};
        const float* r = sW1t + l*LAT;
        #pragma unroll
        for (int q = 0; q < 4; ++q){
            #pragma unroll
            for (int row = 0; row < 4; ++row){
                const ulonglong2 w = *(const ulonglong2*)(r + row*LAT + 4*q);
                pa[row] = fma2(za[2*q], w.x, pa[row]);
                pa[row] = fma2(za[2*q+1], w.y, pa[row]);
                pb[row] = fma2(zb[2*q], w.x, pb[row]);
                pb[row] = fma2(zb[2*q+1], w.y, pb[row]);
            }
        }
        const float4 w2 = *(const float4*)(sw2 + l);
        ya = fmaf(fmaxf(hsum(pa[0]), 0.f), w2.x, ya);
        yb = fmaf(fmaxf(hsum(pb[0]), 0.f), w2.x, yb);
        ya = fmaf(fmaxf(hsum(pa[1]), 0.f), w2.y, ya);
        yb = fmaf(fmaxf(hsum(pb[1]), 0.f), w2.y, yb);
        ya = fmaf(fmaxf(hsum(pa[2]), 0.f), w2.z, ya);
        yb = fmaf(fmaxf(hsum(pb[2]), 0.f), w2.z, yb);
        ya = fmaf(fmaxf(hsum(pa[3]), 0.f), w2.w, ya);
        yb = fmaf(fmaxf(hsum(pb[3]), 0.f), w2.w, yb);
    }
}

__global__ void __launch_bounds__(BS) node_kernel(
    const float* __restrict__ x0,  const float* __restrict__ ts,
    const float* __restrict__ We1, const float* __restrict__ be1,
    const float* __restrict__ We2, const float* __restrict__ be2,
    const float* __restrict__ Wo1, const float* __restrict__ bo1,
    const float* __restrict__ Wo2, const float* __restrict__ bo2,
    const float* __restrict__ Wd1, const float* __restrict__ bd1,
    const float* __restrict__ Wd2, const float* __restrict__ bd2,
    float* __restrict__ out, int B, int T)
{
    __shared__ __align__(16) float sWo1t[HIDP*LAT];  // [l][i] transposed
    __shared__ __align__(16) float sWo2 [HIDP*LAT];  // [l][j]
    __shared__ __align__(16) float sWd1t[HIDP*LAT];  // [l][i] transposed
    __shared__ __align__(16) float sWe2 [HIDP*LAT];  // [l][j]
    __shared__ __align__(16) float sWe1 [2*HIDP];
    __shared__ __align__(16) u64   sbo1p[HIDP];      // (bo1, 0) pairs
    __shared__ __align__(16) u64   sbd1p[HIDP];      // (bd1, 0) pairs
    __shared__ __align__(16) float sbe1 [HIDP];
    __shared__ __align__(16) float sWd2 [HIDP];
    __shared__ __align__(16) float sbo2 [LAT];
    __shared__ __align__(16) float sbe2 [LAT];
    __shared__ __align__(16) u64   sZ [16*BS];       // per-thread z state (2 elems)
    __shared__ __align__(16) u64   sKs[16*BS];       // per-thread RK accumulator
    __shared__ float sT[TSMAX];

    const int tid = threadIdx.x;

    for (int idx = tid; idx < HIDP*LAT; idx += BS){
        const int l = idx / LAT, i = idx - l*LAT;
        const bool v = (l < HID);
        sWo1t[idx] = v ? Wo1[i*HID + l] : 0.f;        // transpose
        sWd1t[idx] = v ? Wd1[i*HID + l] : 0.f;        // transpose
        sWo2 [idx] = v ? Wo2[l*LAT + i] : 0.f;
        sWe2 [idx] = v ? We2[l*LAT + i] : 0.f;
    }
    for (int idx = tid; idx < HIDP; idx += BS){
        const bool v = (idx < HID);
        sbo1p[idx] = pk(v ? bo1[idx] : 0.f, 0.f);
        sbd1p[idx] = pk(v ? bd1[idx] : 0.f, 0.f);
        sbe1[idx] = v ? be1[idx] : 0.f;
        sWd2[idx] = v ? Wd2[idx] : 0.f;
        sWe1[idx]        = v ? We1[idx]       : 0.f;  // row 0 of (2,HID)
        sWe1[HIDP + idx] = v ? We1[HID + idx] : 0.f;  // row 1
    }
    if (tid < LAT){ sbo2[tid] = bo2[tid]; sbe2[tid] = be2[tid]; }
    const int tcap = (T < TSMAX) ? T : TSMAX;
    for (int idx = tid; idx < tcap; idx += BS) sT[idx] = ts[idx];
    __syncthreads();

    const int half = B >> 1;
    const int b0 = blockIdx.x * BS + tid;
    if (b0 >= half) return;
    const int b1 = b0 + half;

    u64* zA = &sZ[tid];             // elem-a state p at zA[p*BS]
    u64* zB = &sZ[8*BS + tid];
    u64* kA = &sKs[tid];
    u64* kB = &sKs[8*BS + tid];

    // ---- encoder for both elements (shared weight loads) ----
    {
        const float2 xa = *(const float2*)(x0 + 2*b0);
        const float2 xb = *(const float2*)(x0 + 2*b1);
        u64 ea[8], eb[8];
        #pragma unroll
        for (int p = 0; p < 8; ++p){ ea[p] = *(const u64*)(sbe2 + 2*p); eb[p] = ea[p]; }
        #pragma unroll 1
        for (int l = 0; l < HID; ++l){
            const float w0 = sWe1[l], w1 = sWe1[HIDP + l], bb = sbe1[l];
            const float hA = fmaxf(fmaf(xa.x, w0, fmaf(xa.y, w1, bb)), 0.f);
            const float hB = fmaxf(fmaf(xb.x, w0, fmaf(xb.y, w1, bb)), 0.f);
            const u64 hda = dup2(hA), hdb = dup2(hB);
            const float* wr = sWe2 + l*LAT;
            #pragma unroll
            for (int q = 0; q < 4; ++q){
                const ulonglong2 w2 = *(const ulonglong2*)(wr + 4*q);
                ea[2*q]     = fma2(hda, w2.x, ea[2*q]);
                ea[2*q + 1] = fma2(hda, w2.y, ea[2*q + 1]);
                eb[2*q]     = fma2(hdb, w2.x, eb[2*q]);
                eb[2*q + 1] = fma2(hdb, w2.y, eb[2*q + 1]);
            }
        }
        #pragma unroll
        for (int p = 0; p < 8; ++p){ zA[p*BS] = ea[p]; zB[p*BS] = eb[p]; }
    }

    u64 za[8], zb[8], ka[8], kb[8];
    const float bd2v = bd2[0];
    const u64 two = dup2(2.0f);

    #pragma unroll 1
    for (int t = 0; t < T; ++t){
        #pragma unroll
        for (int p = 0; p < 8; ++p){ za[p] = zA[p*BS]; zb[p] = zB[p*BS]; }

        float ya, yb;
        dec_f2(za, zb, ya, yb, sWd1t, sbd1p, sWd2, bd2v);
        out[(size_t)t * B + b0] = ya;
        out[(size_t)t * B + b1] = yb;
        if (t == T - 1) break;

        const float dt = (t + 1 < tcap) ? (sT[t+1] - sT[t]) : (ts[t+1] - ts[t]);
        const u64 hdt = dup2(0.5f * dt);
        const u64 fdt = dup2(dt);
        const u64 sdt = dup2(dt * (1.0f/6.0f));

        ode_f2(za, zb, ka, kb, sWo1t, sbo1p, sWo2, sbo2);          // k1
        #pragma unroll
        for (int p = 0; p < 8; ++p){
            kA[p*BS] = ka[p];                      kB[p*BS] = kb[p];
            za[p] = fma2(hdt, ka[p], zA[p*BS]);    zb[p] = fma2(hdt, kb[p], zB[p*BS]);
        }
        ode_f2(za, zb, ka, kb, sWo1t, sbo1p, sWo2, sbo2);          // k2
        #pragma unroll
        for (int p = 0; p < 8; ++p){
            kA[p*BS] = fma2(two, ka[p], kA[p*BS]); kB[p*BS] = fma2(two, kb[p], kB[p*BS]);
            za[p] = fma2(hdt, ka[p], zA[p*BS]);    zb[p] = fma2(hdt, kb[p], zB[p*BS]);
        }
        ode_f2(za, zb, ka, kb, sWo1t, sbo1p, sWo2, sbo2);          // k3
        #pragma unroll
        for (int p = 0; p < 8; ++p){
            kA[p*BS] = fma2(two, ka[p], kA[p*BS]); kB[p*BS] = fma2(two, kb[p], kB[p*BS]);
            za[p] = fma2(fdt, ka[p], zA[p*BS]);    zb[p] = fma2(fdt, kb[p], zB[p*BS]);
        }
        ode_f2(za, zb, ka, kb, sWo1t, sbo1p, sWo2, sbo2);          // k4
        #pragma unroll
        for (int p = 0; p < 8; ++p){
            zA[p*BS] = fma2(sdt, add2(kA[p*BS], ka[p]), zA[p*BS]);
            zB[p*BS] = fma2(sdt, add2(kB[p*BS], kb[p]), zB[p*BS]);
        }
    }
}

extern "C" void kernel_launch(void* const* d_in, const int* in_sizes, int n_in,
                              void* d_out, int out_size)
{
    const float* x0  = (const float*)d_in[0];
    const float* ts  = (const float*)d_in[1];
    const float* We1 = (const float*)d_in[2];
    const float* be1 = (const float*)d_in[3];
    const float* We2 = (const float*)d_in[4];
    const float* be2 = (const float*)d_in[5];
    const float* Wo1 = (const float*)d_in[6];
    const float* bo1 = (const float*)d_in[7];
    const float* Wo2 = (const float*)d_in[8];
    const float* bo2 = (const float*)d_in[9];
    const float* Wd1 = (const float*)d_in[10];
    const float* bd1 = (const float*)d_in[11];
    const float* Wd2 = (const float*)d_in[12];
    const float* bd2 = (const float*)d_in[13];

    const int B = in_sizes[0] / 2;   // (B, 2)
    const int T = in_sizes[1];       // (T,)
    const int half = B / 2;          // 2 elements per thread
    const int grid = (half + BS - 1) / BS;

    node_kernel<<<grid, BS>>>(x0, ts, We1, be1, We2, be2, Wo1, bo1,
                              Wo2, bo2, Wd1, bd1, Wd2, bd2,
                              (float*)d_out, B, T);
}